// round 3
// baseline (speedup 1.0000x reference)
#include <cuda_runtime.h>
#include <cuda_fp16.h>

#define NN 100000
#define NE 1200000
#define NFEAT 64
#define NHID 256
#define NCLS 40

struct __align__(8) EdgeCW { int c; float w; };

__device__ int    g_is64;
__device__ int    g_deg[NN];
__device__ float  g_dinv[NN];
__device__ int    g_rowptr[NN + 1];
__device__ int    g_cursor[NN];
__device__ EdgeCW g_edges[NE];
__device__ __align__(16) __half g_h0[(size_t)NN * NFEAT];
__device__ __align__(16) __half g_h1[(size_t)NN * NFEAT];
__device__ __align__(16) float  g_y [(size_t)NN * NFEAT];

// ---------------------------------------------------------------------------
// Launch 1: detect int64-vs-int32 edge dtype + init degrees (self loop = 1)
// ---------------------------------------------------------------------------
__global__ void setup1_kernel(const int* __restrict__ e32) {
    int i = blockIdx.x * blockDim.x + threadIdx.x;
    if (i == 0) {
        int allz = 1;
        for (int k = 0; k < 64; k++)
            if (e32[2 * k + 1] != 0) { allz = 0; break; }
        g_is64 = allz;
    }
    if (i < NN) g_deg[i] = 1;
}

// Launch 2: degree histogram
__global__ void deg_count_kernel(const void* __restrict__ eptr) {
    int e = blockIdx.x * blockDim.x + threadIdx.x;
    if (e >= NE) return;
    int r;
    if (g_is64) r = (int)((const long long*)eptr)[e];
    else        r = ((const int*)eptr)[e];
    atomicAdd(&g_deg[r], 1);
}

// Launch 3: fused dinv + exclusive scan (single block, 1024 threads)
__global__ void dinv_scan_kernel() {
    __shared__ int part[1024];
    int t = threadIdx.x;
    const int CH = (NN + 1023) / 1024;  // 98
    int base = t * CH;
    int s = 0;
    for (int i = 0; i < CH; i++) {
        int idx = base + i;
        if (idx < NN) {
            int d = g_deg[idx];
            g_dinv[idx] = rsqrtf((float)d);
            s += d - 1;
        }
    }
    part[t] = s;
    __syncthreads();
    for (int off = 1; off < 1024; off <<= 1) {
        int v = 0;
        if (t >= off) v = part[t - off];
        __syncthreads();
        if (t >= off) part[t] += v;
        __syncthreads();
    }
    int run = (t == 0) ? 0 : part[t - 1];
    for (int i = 0; i < CH; i++) {
        int idx = base + i;
        if (idx < NN) {
            g_rowptr[idx] = run;
            g_cursor[idx] = run;
            run += g_deg[idx] - 1;
        }
    }
    if (t == 1023) g_rowptr[NN] = part[1023];
}

// Launch 4: CSR fill (atomic scatter) + h0/y init fused
__global__ void fill_init_kernel(const void* __restrict__ eptr,
                                 const float* __restrict__ x) {
    int i = blockIdx.x * blockDim.x + threadIdx.x;
    if (i < NE) {
        int r, c;
        if (g_is64) {
            const long long* q = (const long long*)eptr;
            r = (int)q[i]; c = (int)q[i + NE];
        } else {
            const int* q = (const int*)eptr;
            r = q[i]; c = q[i + NE];
        }
        int pos = atomicAdd(&g_cursor[r], 1);
        EdgeCW ec;
        ec.c = c;
        ec.w = g_dinv[r] * g_dinv[c];
        g_edges[pos] = ec;
    }
    if (i < NN * (NFEAT / 4)) {
        float4 v = ((const float4*)x)[i];
        v.x *= 0.5f; v.y *= 0.5f; v.z *= 0.5f; v.w *= 0.5f;
        ((float4*)g_y)[i] = v;
        __half2* h2 = (__half2*)g_h0;
        h2[2 * i]     = __floats2half2_rn(v.x, v.y);
        h2[2 * i + 1] = __floats2half2_rn(v.z, v.w);
    }
}

// ---------------------------------------------------------------------------
// SpMM: one warp per row, split into 4 quarters of 8 lanes.
// Each lane loads 16B (8 fp16 features) of its quarter's edge row, so one
// warp-wide LDG.128 covers 4 edges. 2-stage software pipeline keeps the next
// group's gather in flight during the current group's FMAs.
// dst[r] = dinv[r]^2*src[r] + sum ew*src[col];  y[r] += dst[r]
// ---------------------------------------------------------------------------
__device__ __forceinline__ void accum8(float acc[8], int4 v, float w) {
    __half2* h = (__half2*)&v;
    #pragma unroll
    for (int i = 0; i < 4; i++) {
        float2 f = __half22float2(h[i]);
        acc[2 * i]     = fmaf(w, f.x, acc[2 * i]);
        acc[2 * i + 1] = fmaf(w, f.y, acc[2 * i + 1]);
    }
}

__global__ void __launch_bounds__(256) spmm_kernel(int sel) {
    const int4* __restrict__ src = (const int4*)(sel ? g_h1 : g_h0);
    int4*       __restrict__ dst = (int4*)(sel ? g_h0 : g_h1);
    int gw = (blockIdx.x * blockDim.x + threadIdx.x) >> 5;
    if (gw >= NN) return;
    int lane = threadIdx.x & 31;
    int q = lane >> 3, sub = lane & 7;

    int beg = g_rowptr[gw];
    int end = g_rowptr[gw + 1];

    float acc[8];
    #pragma unroll
    for (int i = 0; i < 8; i++) acc[i] = 0.f;

    for (int j0 = beg; j0 < end; j0 += 32) {
        int n = end - j0; if (n > 32) n = 32;
        int   ec = 0;
        float ew = 0.f;
        if (lane < n) {
            EdgeCW e = g_edges[j0 + lane];
            ec = e.c; ew = e.w;
        }
        int gcnt = (n + 3) >> 2;  // groups of 4 edges

        // prefetch group 0
        int   cc = __shfl_sync(0xffffffffu, ec, q);
        float ww = __shfl_sync(0xffffffffu, ew, q);
        int4  v  = src[cc * 8 + sub];

        for (int g = 1; g < gcnt; g++) {
            int slot = g * 4 + q;
            int   cc2 = __shfl_sync(0xffffffffu, ec, slot);
            float ww2 = __shfl_sync(0xffffffffu, ew, slot);
            int4  v2  = src[cc2 * 8 + sub];
            accum8(acc, v, ww);
            v = v2; ww = ww2;
        }
        accum8(acc, v, ww);
    }

    // reduce partials across the 4 quarters (same sub -> same features)
    #pragma unroll
    for (int i = 0; i < 8; i++) {
        acc[i] += __shfl_xor_sync(0xffffffffu, acc[i], 8);
        acc[i] += __shfl_xor_sync(0xffffffffu, acc[i], 16);
    }

    // self loop (after reduction: add exactly once)
    float di = g_dinv[gw];
    float sw = di * di;
    int4 svi = src[gw * 8 + sub];
    {
        __half2* h = (__half2*)&svi;
        #pragma unroll
        for (int i = 0; i < 4; i++) {
            float2 f = __half22float2(h[i]);
            acc[2 * i]     = fmaf(sw, f.x, acc[2 * i]);
            acc[2 * i + 1] = fmaf(sw, f.y, acc[2 * i + 1]);
        }
    }

    // store dst: 8 lanes (q==0) write 16B each
    if (q == 0) {
        __half2 p[4];
        #pragma unroll
        for (int i = 0; i < 4; i++)
            p[i] = __floats2half2_rn(acc[2 * i], acc[2 * i + 1]);
        dst[gw * 8 + sub] = *(int4*)p;
    }

    // y update: 16 lanes (q<2) each RMW one float4
    if (q < 2) {
        float4* y4 = (float4*)g_y;
        int fi = gw * 16 + sub * 2 + q;
        float4 yv = y4[fi];
        yv.x += acc[q * 4 + 0];
        yv.y += acc[q * 4 + 1];
        yv.z += acc[q * 4 + 2];
        yv.w += acc[q * 4 + 3];
        y4[fi] = yv;
    }
}

// ---------------------------------------------------------------------------
// Fused MLP: out = relu((y/9) @ W1 + b1) @ W2 + b2
// ---------------------------------------------------------------------------
#define MLP_SMEM_FLOATS (64 * 256 + 256 * 40 + 64 * 65 + 64 * 264)

__global__ void __launch_bounds__(256) mlp_kernel(
    const float* __restrict__ W1g, const float* __restrict__ b1g,
    const float* __restrict__ W2g, const float* __restrict__ b2g,
    float* __restrict__ out)
{
    extern __shared__ float sm[];
    float* sW1 = sm;                     // [f][c]  64 x 256 (scaled by 1/9)
    float* sW2 = sW1 + 64 * 256;         // [k][c]  256 x 40
    float* sY  = sW2 + 256 * 40;         // [r][f]  64 x 65 (pad)
    float* sH  = sY  + 64 * 65;          // [r][k]  64 x 264 (pad)

    int t = threadIdx.x;
    int row0 = blockIdx.x * 64;

    for (int i = t; i < 64 * 64; i += 256) {
        int r = i >> 6, f = i & 63;
        float v = (row0 + r < NN) ? g_y[(size_t)(row0 + r) * 64 + f] : 0.f;
        sY[r * 65 + f] = v;
    }
    const float inv9 = 1.0f / 9.0f;
    for (int i = t; i < 64 * 256; i += 256) sW1[i] = W1g[i] * inv9;
    for (int i = t; i < 256 * 40; i += 256) sW2[i] = W2g[i];
    __syncthreads();

    // Phase 1: hid[64][256] = relu(Y @ W1 + b1)
    {
        int rg = t & 7;
        int cg = t >> 3;
        float acc[8][8];
        #pragma unroll
        for (int i = 0; i < 8; i++)
            #pragma unroll
            for (int j = 0; j < 8; j++) acc[i][j] = 0.f;

        #pragma unroll 4
        for (int f = 0; f < 64; f++) {
            float a[8];
            #pragma unroll
            for (int i = 0; i < 8; i++) a[i] = sY[(8 * rg + i) * 65 + f];
            float4 w0 = *(const float4*)&sW1[f * 256 + 8 * cg];
            float4 w1 = *(const float4*)&sW1[f * 256 + 8 * cg + 4];
            float w[8] = {w0.x, w0.y, w0.z, w0.w, w1.x, w1.y, w1.z, w1.w};
            #pragma unroll
            for (int i = 0; i < 8; i++)
                #pragma unroll
                for (int j = 0; j < 8; j++)
                    acc[i][j] = fmaf(a[i], w[j], acc[i][j]);
        }

        float bv[8];
        #pragma unroll
        for (int j = 0; j < 8; j++) bv[j] = __ldg(&b1g[8 * cg + j]);
        #pragma unroll
        for (int i = 0; i < 8; i++)
            #pragma unroll
            for (int j = 0; j < 8; j++)
                sH[(8 * rg + i) * 264 + 8 * cg + j] = fmaxf(acc[i][j] + bv[j], 0.f);
    }
    __syncthreads();

    // Phase 2: out[64][40] = hid @ W2 + b2
    {
        int r  = t >> 2;
        int cq = t & 3;
        int c0 = cq * 10;
        float acc2[10];
        #pragma unroll
        for (int j = 0; j < 10; j++) acc2[j] = __ldg(&b2g[c0 + j]);

        #pragma unroll 2
        for (int k = 0; k < 256; k++) {
            float hv = sH[r * 264 + k];
            #pragma unroll
            for (int j2 = 0; j2 < 5; j2++) {
                float2 w = *(const float2*)&sW2[k * 40 + c0 + 2 * j2];
                acc2[2 * j2]     = fmaf(hv, w.x, acc2[2 * j2]);
                acc2[2 * j2 + 1] = fmaf(hv, w.y, acc2[2 * j2 + 1]);
            }
        }
        if (row0 + r < NN) {
            #pragma unroll
            for (int j = 0; j < 10; j++)
                out[(size_t)(row0 + r) * 40 + c0 + j] = acc2[j];
        }
    }
}

extern "C" void kernel_launch(void* const* d_in, const int* in_sizes, int n_in,
                              void* d_out, int out_size) {
    const float* x   = (const float*)d_in[0];
    const void*  eix = d_in[1];
    const float* W1  = (const float*)d_in[2];
    const float* b1  = (const float*)d_in[3];
    const float* W2  = (const float*)d_in[4];
    const float* b2  = (const float*)d_in[5];
    float* out = (float*)d_out;

    cudaFuncSetAttribute(mlp_kernel, cudaFuncAttributeMaxDynamicSharedMemorySize,
                         MLP_SMEM_FLOATS * (int)sizeof(float));

    setup1_kernel<<<(NN + 255) / 256, 256>>>((const int*)eix);
    deg_count_kernel<<<(NE + 255) / 256, 256>>>(eix);
    dinv_scan_kernel<<<1, 1024>>>();
    int fi_threads = NN * (NFEAT / 4);
    fill_init_kernel<<<(fi_threads + 255) / 256, 256>>>(eix, x);

    int spmm_blocks = (NN * 32 + 255) / 256;
    for (int it = 0; it < 8; it++)
        spmm_kernel<<<spmm_blocks, 256>>>(it & 1);

    int mlp_blocks = (NN + 63) / 64;
    mlp_kernel<<<mlp_blocks, 256, MLP_SMEM_FLOATS * (int)sizeof(float)>>>(
        W1, b1, W2, b2, out);
}

// round 4
// speedup vs baseline: 1.1598x; 1.1598x over previous
#include <cuda_runtime.h>
#include <cuda_fp16.h>

#define NN 100000
#define NE 1200000
#define NFEAT 64
#define NHID 256
#define NCLS 40

struct __align__(8) EdgeCW { int c; float w; };

__device__ int    g_deg[NN];          // real-edge counts (memset to 0)
__device__ float  g_dinv[NN];
__device__ int    g_rowptr[NN + 1];
__device__ int    g_cursor[NN];
__device__ EdgeCW g_edges[NE];
__device__ __align__(16) __half g_h0[(size_t)NN * NFEAT];
__device__ __align__(16) __half g_h1[(size_t)NN * NFEAT];
__device__ __align__(16) float  g_y [(size_t)NN * NFEAT];

// Per-block int64-vs-int32 detection: high words of the first 64 candidate
// int64 values are all zero iff dtype is int64 (values < 100000).
__device__ __forceinline__ int detect_is64_block(const int* e32, int tid) {
    __shared__ int s_is64;
    if (tid == 0) {
        int allz = 1;
        for (int k = 0; k < 64; k++)
            if (e32[2 * k + 1] != 0) { allz = 0; break; }
        s_is64 = allz;
    }
    __syncthreads();
    return s_is64;
}

// Launch 1: degree histogram (g_deg pre-zeroed via memset node)
__global__ void deg_count_kernel(const void* __restrict__ eptr) {
    int is64 = detect_is64_block((const int*)eptr, threadIdx.x);
    int e = blockIdx.x * blockDim.x + threadIdx.x;
    if (e >= NE) return;
    int r;
    if (is64) r = (int)((const long long*)eptr)[e];
    else      r = ((const int*)eptr)[e];
    atomicAdd(&g_deg[r], 1);
}

// Launch 2: fused dinv + exclusive scan (single block, 1024 threads)
// dinv uses deg+1 (self loop); scan is over real-edge counts.
__global__ void dinv_scan_kernel() {
    __shared__ int part[1024];
    int t = threadIdx.x;
    const int CH = (NN + 1023) / 1024;  // 98
    int base = t * CH;
    int s = 0;
    for (int i = 0; i < CH; i++) {
        int idx = base + i;
        if (idx < NN) {
            int d = g_deg[idx];
            g_dinv[idx] = rsqrtf((float)(d + 1));
            s += d;
        }
    }
    part[t] = s;
    __syncthreads();
    for (int off = 1; off < 1024; off <<= 1) {
        int v = 0;
        if (t >= off) v = part[t - off];
        __syncthreads();
        if (t >= off) part[t] += v;
        __syncthreads();
    }
    int run = (t == 0) ? 0 : part[t - 1];
    for (int i = 0; i < CH; i++) {
        int idx = base + i;
        if (idx < NN) {
            g_rowptr[idx] = run;
            g_cursor[idx] = run;
            run += g_deg[idx];
        }
    }
    if (t == 1023) g_rowptr[NN] = part[1023];
}

// Launch 3: CSR fill (atomic scatter) + h0/y init fused
__global__ void fill_init_kernel(const void* __restrict__ eptr,
                                 const float* __restrict__ x) {
    int is64 = detect_is64_block((const int*)eptr, threadIdx.x);
    int i = blockIdx.x * blockDim.x + threadIdx.x;
    if (i < NE) {
        int r, c;
        if (is64) {
            const long long* q = (const long long*)eptr;
            r = (int)q[i]; c = (int)q[i + NE];
        } else {
            const int* q = (const int*)eptr;
            r = q[i]; c = q[i + NE];
        }
        int pos = atomicAdd(&g_cursor[r], 1);
        EdgeCW ec;
        ec.c = c;
        ec.w = g_dinv[r] * g_dinv[c];
        g_edges[pos] = ec;
    }
    if (i < NN * (NFEAT / 4)) {
        float4 v = ((const float4*)x)[i];
        v.x *= 0.5f; v.y *= 0.5f; v.z *= 0.5f; v.w *= 0.5f;
        ((float4*)g_y)[i] = v;
        __half2* h2 = (__half2*)g_h0;
        h2[2 * i]     = __floats2half2_rn(v.x, v.y);
        h2[2 * i + 1] = __floats2half2_rn(v.z, v.w);
    }
}

// ---------------------------------------------------------------------------
// SpMM (round-2 form, best so far): one warp per row, lane-parallel edge
// fetch, shfl broadcast, fp16 h / fp32 accumulate.
// dst[r] = dinv[r]^2*src[r] + sum ew*src[col];  y[r] += dst[r]
// ---------------------------------------------------------------------------
__global__ void __launch_bounds__(256) spmm_kernel(int sel) {
    const __half2* __restrict__ src = (const __half2*)(sel ? g_h1 : g_h0);
    __half2*       __restrict__ dst = (__half2*)(sel ? g_h0 : g_h1);
    int gw = (blockIdx.x * blockDim.x + threadIdx.x) >> 5;
    if (gw >= NN) return;
    int lane = threadIdx.x & 31;

    int beg = g_rowptr[gw];
    int end = g_rowptr[gw + 1];
    float di = g_dinv[gw];
    float sw = di * di;

    float2 sv = __half22float2(src[gw * 32 + lane]);
    float2 acc;
    acc.x = sw * sv.x;
    acc.y = sw * sv.y;

    for (int j0 = beg; j0 < end; j0 += 32) {
        int rem = end - j0;
        int n = rem < 32 ? rem : 32;
        int   ec = 0;
        float ew = 0.f;
        if (lane < n) {
            EdgeCW e = g_edges[j0 + lane];
            ec = e.c; ew = e.w;
        }
        for (int k = 0; k < n; k++) {
            int   cc = __shfl_sync(0xffffffffu, ec, k);
            float ww = __shfl_sync(0xffffffffu, ew, k);
            float2 hv = __half22float2(src[cc * 32 + lane]);
            acc.x = fmaf(ww, hv.x, acc.x);
            acc.y = fmaf(ww, hv.y, acc.y);
        }
    }

    dst[gw * 32 + lane] = __floats2half2_rn(acc.x, acc.y);
    float2* y2 = (float2*)g_y;
    float2 yv = y2[gw * 32 + lane];
    yv.x += acc.x;
    yv.y += acc.y;
    y2[gw * 32 + lane] = yv;
}

// ---------------------------------------------------------------------------
// Fused MLP: out = relu((y/9) @ W1 + b1) @ W2 + b2
// ---------------------------------------------------------------------------
#define MLP_SMEM_FLOATS (64 * 256 + 256 * 40 + 64 * 65 + 64 * 264)

__global__ void __launch_bounds__(256) mlp_kernel(
    const float* __restrict__ W1g, const float* __restrict__ b1g,
    const float* __restrict__ W2g, const float* __restrict__ b2g,
    float* __restrict__ out)
{
    extern __shared__ float sm[];
    float* sW1 = sm;                     // [f][c]  64 x 256 (scaled by 1/9)
    float* sW2 = sW1 + 64 * 256;         // [k][c]  256 x 40
    float* sY  = sW2 + 256 * 40;         // [r][f]  64 x 65 (pad)
    float* sH  = sY  + 64 * 65;          // [r][k]  64 x 264 (pad)

    int t = threadIdx.x;
    int row0 = blockIdx.x * 64;

    // Stage tiles (vectorized)
    const float inv9 = 1.0f / 9.0f;
    {
        const float4* W14 = (const float4*)W1g;
        #pragma unroll
        for (int i = t; i < 64 * 256 / 4; i += 256) {
            float4 v = W14[i];
            v.x *= inv9; v.y *= inv9; v.z *= inv9; v.w *= inv9;
            ((float4*)sW1)[i] = v;
        }
        const float4* W24 = (const float4*)W2g;
        #pragma unroll
        for (int i = t; i < 256 * 40 / 4; i += 256) {
            ((float4*)sW2)[i] = W24[i];
        }
        // Y tile: 64 rows x 64 feats = 1024 float4
        const float4* Y4 = (const float4*)g_y;
        bool full = (row0 + 64 <= NN);
        for (int i = t; i < 64 * 16; i += 256) {
            int r = i >> 4, f4 = i & 15;
            float4 v = make_float4(0.f, 0.f, 0.f, 0.f);
            if (full || row0 + r < NN) v = Y4[(size_t)(row0 + r) * 16 + f4];
            float* d = &sY[r * 65 + f4 * 4];
            d[0] = v.x; d[1] = v.y; d[2] = v.z; d[3] = v.w;
        }
    }
    __syncthreads();

    // Phase 1: hid[64][256] = relu(Y @ W1 + b1)
    {
        int rg = t & 7;
        int cg = t >> 3;
        float acc[8][8];
        #pragma unroll
        for (int i = 0; i < 8; i++)
            #pragma unroll
            for (int j = 0; j < 8; j++) acc[i][j] = 0.f;

        #pragma unroll 4
        for (int f = 0; f < 64; f++) {
            float a[8];
            #pragma unroll
            for (int i = 0; i < 8; i++) a[i] = sY[(8 * rg + i) * 65 + f];
            float4 w0 = *(const float4*)&sW1[f * 256 + 8 * cg];
            float4 w1 = *(const float4*)&sW1[f * 256 + 8 * cg + 4];
            float w[8] = {w0.x, w0.y, w0.z, w0.w, w1.x, w1.y, w1.z, w1.w};
            #pragma unroll
            for (int i = 0; i < 8; i++)
                #pragma unroll
                for (int j = 0; j < 8; j++)
                    acc[i][j] = fmaf(a[i], w[j], acc[i][j]);
        }

        float bv[8];
        #pragma unroll
        for (int j = 0; j < 8; j++) bv[j] = __ldg(&b1g[8 * cg + j]);
        #pragma unroll
        for (int i = 0; i < 8; i++)
            #pragma unroll
            for (int j = 0; j < 8; j++)
                sH[(8 * rg + i) * 264 + 8 * cg + j] = fmaxf(acc[i][j] + bv[j], 0.f);
    }
    __syncthreads();

    // Phase 2: out[64][40] = hid @ W2 + b2
    {
        int r  = t >> 2;
        int cq = t & 3;
        int c0 = cq * 10;
        float acc2[10];
        #pragma unroll
        for (int j = 0; j < 10; j++) acc2[j] = __ldg(&b2g[c0 + j]);

        #pragma unroll 2
        for (int k = 0; k < 256; k++) {
            float hv = sH[r * 264 + k];
            #pragma unroll
            for (int j2 = 0; j2 < 5; j2++) {
                float2 w = *(const float2*)&sW2[k * 40 + c0 + 2 * j2];
                acc2[2 * j2]     = fmaf(hv, w.x, acc2[2 * j2]);
                acc2[2 * j2 + 1] = fmaf(hv, w.y, acc2[2 * j2 + 1]);
            }
        }
        if (row0 + r < NN) {
            #pragma unroll
            for (int j = 0; j < 10; j++)
                out[(size_t)(row0 + r) * 40 + c0 + j] = acc2[j];
        }
    }
}

extern "C" void kernel_launch(void* const* d_in, const int* in_sizes, int n_in,
                              void* d_out, int out_size) {
    const float* x   = (const float*)d_in[0];
    const void*  eix = d_in[1];
    const float* W1  = (const float*)d_in[2];
    const float* b1  = (const float*)d_in[3];
    const float* W2  = (const float*)d_in[4];
    const float* b2  = (const float*)d_in[5];
    float* out = (float*)d_out;

    cudaFuncSetAttribute(mlp_kernel, cudaFuncAttributeMaxDynamicSharedMemorySize,
                         MLP_SMEM_FLOATS * (int)sizeof(float));

    // memset node (not a kernel launch): zero the degree histogram
    void* deg_ptr = nullptr;
    cudaGetSymbolAddress(&deg_ptr, g_deg);
    cudaMemsetAsync(deg_ptr, 0, NN * sizeof(int));

    deg_count_kernel<<<(NE + 255) / 256, 256>>>(eix);          // launch 1
    dinv_scan_kernel<<<1, 1024>>>();                           // launch 2
    int fi_threads = NN * (NFEAT / 4);
    fill_init_kernel<<<(fi_threads + 255) / 256, 256>>>(eix, x); // launch 3

    int spmm_blocks = (NN * 32 + 255) / 256;
    for (int it = 0; it < 8; it++)                             // launches 4-11
        spmm_kernel<<<spmm_blocks, 256>>>(it & 1);

    int mlp_blocks = (NN + 63) / 64;
    mlp_kernel<<<mlp_blocks, 256, MLP_SMEM_FLOATS * (int)sizeof(float)>>>(
        W1, b1, W2, b2, out);                                  // launch 12
}